// round 1
// baseline (speedup 1.0000x reference)
#include <cuda_runtime.h>

#define B_ROWS 16384
#define C_DIM  1024
#define N_ITERS 16

// GEMM tiling
#define BM 128
#define BN 128
#define BK 16
#define BKP 20            // padded K stride: conflict-free frag loads + 16B-aligned float4 STS
#define GEMM_THREADS 256

// ---------------- static scratch (no allocations allowed) ----------------
__device__ float g_h1[(size_t)B_ROWS * C_DIM];
__device__ float g_d1[(size_t)B_ROWS * C_DIM];
__device__ float g_h2[(size_t)B_ROWS * C_DIM];
__device__ float g_d2[(size_t)B_ROWS * C_DIM];
__device__ float g_t1[(size_t)B_ROWS * C_DIM];
__device__ float g_t2[(size_t)B_ROWS * C_DIM];
__device__ float g_w [(size_t)B_ROWS * C_DIM];
__device__ float g_w1t[(size_t)C_DIM * C_DIM];
__device__ float g_w2t[(size_t)C_DIM * C_DIM];
__device__ float g_w3t[(size_t)C_DIM * C_DIM];

// ---------------- helpers ----------------
__device__ __forceinline__ float to_tf32(float x) {
    unsigned r;
    asm("cvt.rna.tf32.f32 %0, %1;" : "=r"(r) : "f"(x));
    return __uint_as_float(r);
}

#define MMA_TF32(C0, C1, C2, C3, A0, A1, A2, A3, Bb0, Bb1)                          \
    asm volatile(                                                                   \
        "mma.sync.aligned.m16n8k8.row.col.f32.tf32.tf32.f32 "                       \
        "{%0,%1,%2,%3}, {%4,%5,%6,%7}, {%8,%9}, {%0,%1,%2,%3};"                     \
        : "+f"(C0), "+f"(C1), "+f"(C2), "+f"(C3)                                    \
        : "r"(A0), "r"(A1), "r"(A2), "r"(A3), "r"(Bb0), "r"(Bb1))

constexpr int EPI_ELU  = 0;  // out0 = elu(c+bias), out1 = elu'(c+bias)
constexpr int EPI_ADDY = 1;  // out0 = aux + c + bias          (z = y + g)
constexpr int EPI_MULD = 2;  // out0 = c * aux                 (apply elu' mask)
constexpr int EPI_LAST = 3;  // out0 = c; acc[row] += alpha * sum_col(c*aux)

// NT GEMM: out[m,n] = sum_k A[m,k] * Bm[n,k];  M=B_ROWS, N=K=C_DIM
template <int EPI>
__global__ __launch_bounds__(GEMM_THREADS, 2)
void gemm_nt(const float* __restrict__ A, const float* __restrict__ Bm,
             const float* __restrict__ bias,
             float* __restrict__ out0, float* __restrict__ out1,
             const float* __restrict__ aux,
             float alpha, float* __restrict__ acc)
{
    __shared__ __align__(16) float As[2][BM][BKP];
    __shared__ __align__(16) float Bs[2][BN][BKP];

    const int tid  = threadIdx.x;
    const int lane = tid & 31;
    const int warp = tid >> 5;
    const int wm   = warp & 3;   // 4 warps along M (32 rows each)
    const int wn   = warp >> 2;  // 2 warps along N (64 cols each)
    const int g    = lane >> 2;  // groupID
    const int t    = lane & 3;   // threadID in group

    const int brow = blockIdx.y * BM;
    const int bcol = blockIdx.x * BN;

    // global staging: 2 float4 per thread per operand
    const int f0 = tid,               r0 = f0 >> 2, c0 = (f0 & 3) * 4;
    const int f1 = tid + GEMM_THREADS, r1 = f1 >> 2, c1 = (f1 & 3) * 4;
    const float* Ap0 = A  + (size_t)(brow + r0) * C_DIM + c0;
    const float* Ap1 = A  + (size_t)(brow + r1) * C_DIM + c1;
    const float* Bp0 = Bm + (size_t)(bcol + r0) * C_DIM + c0;
    const float* Bp1 = Bm + (size_t)(bcol + r1) * C_DIM + c1;

    float c[2][8][4];
#pragma unroll
    for (int i = 0; i < 2; ++i)
#pragma unroll
        for (int j = 0; j < 8; ++j)
#pragma unroll
            for (int r = 0; r < 4; ++r) c[i][j][r] = 0.f;

    float4 va0, va1, vb0, vb1;

#define LDG_TILE(kt)                                        \
    do {                                                    \
        va0 = *(const float4*)(Ap0 + (kt) * BK);            \
        va1 = *(const float4*)(Ap1 + (kt) * BK);            \
        vb0 = *(const float4*)(Bp0 + (kt) * BK);            \
        vb1 = *(const float4*)(Bp1 + (kt) * BK);            \
    } while (0)

#define STS_TILE(buf)                                                           \
    do {                                                                        \
        float4 w_;                                                              \
        w_ = va0; w_.x = to_tf32(w_.x); w_.y = to_tf32(w_.y);                   \
        w_.z = to_tf32(w_.z); w_.w = to_tf32(w_.w);                             \
        *(float4*)&As[buf][r0][c0] = w_;                                        \
        w_ = va1; w_.x = to_tf32(w_.x); w_.y = to_tf32(w_.y);                   \
        w_.z = to_tf32(w_.z); w_.w = to_tf32(w_.w);                             \
        *(float4*)&As[buf][r1][c1] = w_;                                        \
        w_ = vb0; w_.x = to_tf32(w_.x); w_.y = to_tf32(w_.y);                   \
        w_.z = to_tf32(w_.z); w_.w = to_tf32(w_.w);                             \
        *(float4*)&Bs[buf][r0][c0] = w_;                                        \
        w_ = vb1; w_.x = to_tf32(w_.x); w_.y = to_tf32(w_.y);                   \
        w_.z = to_tf32(w_.z); w_.w = to_tf32(w_.w);                             \
        *(float4*)&Bs[buf][r1][c1] = w_;                                        \
    } while (0)

    LDG_TILE(0);
    STS_TILE(0);
    __syncthreads();

    const int KT = C_DIM / BK;  // 64
#pragma unroll 1
    for (int kt = 0; kt < KT; ++kt) {
        const int cur = kt & 1;
        if (kt + 1 < KT) LDG_TILE(kt + 1);

#pragma unroll
        for (int ks = 0; ks < 2; ++ks) {
            const int k0 = ks * 8;
            unsigned af[2][4];
            unsigned bfr[8][2];
#pragma unroll
            for (int mt = 0; mt < 2; ++mt) {
                const float* ap = &As[cur][wm * 32 + mt * 16][k0];
                af[mt][0] = __float_as_uint(ap[g * BKP + t]);
                af[mt][1] = __float_as_uint(ap[(g + 8) * BKP + t]);
                af[mt][2] = __float_as_uint(ap[g * BKP + t + 4]);
                af[mt][3] = __float_as_uint(ap[(g + 8) * BKP + t + 4]);
            }
#pragma unroll
            for (int nt = 0; nt < 8; ++nt) {
                const float* bp = &Bs[cur][wn * 64 + nt * 8 + g][k0];
                bfr[nt][0] = __float_as_uint(bp[t]);
                bfr[nt][1] = __float_as_uint(bp[t + 4]);
            }
#pragma unroll
            for (int mt = 0; mt < 2; ++mt)
#pragma unroll
                for (int nt = 0; nt < 8; ++nt)
                    MMA_TF32(c[mt][nt][0], c[mt][nt][1], c[mt][nt][2], c[mt][nt][3],
                             af[mt][0], af[mt][1], af[mt][2], af[mt][3],
                             bfr[nt][0], bfr[nt][1]);
        }

        if (kt + 1 < KT) STS_TILE(cur ^ 1);
        __syncthreads();
    }
#undef LDG_TILE
#undef STS_TILE

    // ---------------- epilogue ----------------
    float rs[2][2];
    rs[0][0] = rs[0][1] = rs[1][0] = rs[1][1] = 0.f;

#pragma unroll
    for (int mt = 0; mt < 2; ++mt) {
        const int row0 = brow + wm * 32 + mt * 16 + g;
#pragma unroll
        for (int nt = 0; nt < 8; ++nt) {
            const int col = bcol + wn * 64 + nt * 8 + 2 * t;
#pragma unroll
            for (int h = 0; h < 2; ++h) {
                const int row = row0 + h * 8;
                const size_t idx = (size_t)row * C_DIM + col;
                float v0 = c[mt][nt][h * 2 + 0];
                float v1 = c[mt][nt][h * 2 + 1];
                if (EPI == EPI_ELU) {
                    float2 bb = *(const float2*)&bias[col];
                    float a0 = v0 + bb.x, a1 = v1 + bb.y;
                    float h0 = (a0 > 0.f) ? a0 : expm1f(a0);
                    float h1 = (a1 > 0.f) ? a1 : expm1f(a1);
                    float e0 = (a0 > 0.f) ? 1.f : h0 + 1.f;
                    float e1 = (a1 > 0.f) ? 1.f : h1 + 1.f;
                    *(float2*)&out0[idx] = make_float2(h0, h1);
                    *(float2*)&out1[idx] = make_float2(e0, e1);
                } else if (EPI == EPI_ADDY) {
                    float2 bb = *(const float2*)&bias[col];
                    float2 yv = *(const float2*)&aux[idx];
                    *(float2*)&out0[idx] = make_float2(v0 + bb.x + yv.x, v1 + bb.y + yv.y);
                } else if (EPI == EPI_MULD) {
                    float2 dv = *(const float2*)&aux[idx];
                    *(float2*)&out0[idx] = make_float2(v0 * dv.x, v1 * dv.y);
                } else {  // EPI_LAST
                    float2 vv = *(const float2*)&aux[idx];
                    *(float2*)&out0[idx] = make_float2(v0, v1);
                    rs[mt][h] += v0 * vv.x + v1 * vv.y;
                }
            }
        }
    }

    if (EPI == EPI_LAST) {
#pragma unroll
        for (int mt = 0; mt < 2; ++mt)
#pragma unroll
            for (int h = 0; h < 2; ++h) {
                float s = rs[mt][h];
                s += __shfl_xor_sync(0xffffffffu, s, 1);
                s += __shfl_xor_sync(0xffffffffu, s, 2);
                if (t == 0)
                    atomicAdd(&acc[brow + wm * 32 + mt * 16 + g + h * 8], alpha * s);
            }
    }
}

// 1024x1024 transpose
__global__ void transpose_k(const float* __restrict__ in, float* __restrict__ out)
{
    __shared__ float tile[32][33];
    int x = blockIdx.x * 32 + threadIdx.x;
    int y = blockIdx.y * 32 + threadIdx.y;
#pragma unroll
    for (int i = 0; i < 32; i += 8)
        tile[threadIdx.y + i][threadIdx.x] = in[(size_t)(y + i) * C_DIM + x];
    __syncthreads();
    x = blockIdx.y * 32 + threadIdx.x;
    y = blockIdx.x * 32 + threadIdx.y;
#pragma unroll
    for (int i = 0; i < 32; i += 8)
        out[(size_t)(y + i) * C_DIM + x] = tile[threadIdx.x][threadIdx.y + i];
}

__global__ void copy_f32(const float* __restrict__ in, float* __restrict__ out, int n)
{
    int i = blockIdx.x * blockDim.x + threadIdx.x;
    if (i < n) out[i] = in[i];
}

// ---------------- launch ----------------
extern "C" void kernel_launch(void* const* d_in, const int* in_sizes, int n_in,
                              void* d_out, int out_size)
{
    (void)in_sizes; (void)n_in; (void)out_size;

    const float* y   = (const float*)d_in[0];
    const float* ldj = (const float*)d_in[1];
    const float* v   = (const float*)d_in[2];
    const float* W1  = (const float*)d_in[3];
    const float* b1  = (const float*)d_in[4];
    const float* W2  = (const float*)d_in[5];
    const float* b2  = (const float*)d_in[6];
    const float* W3  = (const float*)d_in[7];
    const float* b3  = (const float*)d_in[8];

    float* zout  = (float*)d_out;
    float* ldout = zout + (size_t)B_ROWS * C_DIM;

    float *h1, *d1, *h2, *d2, *t1, *t2, *wb, *w1t, *w2t, *w3t;
    cudaGetSymbolAddress((void**)&h1,  g_h1);
    cudaGetSymbolAddress((void**)&d1,  g_d1);
    cudaGetSymbolAddress((void**)&h2,  g_h2);
    cudaGetSymbolAddress((void**)&d2,  g_d2);
    cudaGetSymbolAddress((void**)&t1,  g_t1);
    cudaGetSymbolAddress((void**)&t2,  g_t2);
    cudaGetSymbolAddress((void**)&wb,  g_w);
    cudaGetSymbolAddress((void**)&w1t, g_w1t);
    cudaGetSymbolAddress((void**)&w2t, g_w2t);
    cudaGetSymbolAddress((void**)&w3t, g_w3t);

    dim3 tgrid(C_DIM / 32, C_DIM / 32), tblk(32, 8);
    transpose_k<<<tgrid, tblk>>>(W1, w1t);
    transpose_k<<<tgrid, tblk>>>(W2, w2t);
    transpose_k<<<tgrid, tblk>>>(W3, w3t);

    // logdet output starts as the input log_det_jacobians; iterations atomically add into it
    copy_f32<<<B_ROWS / 256, 256>>>(ldj, ldout, B_ROWS);

    dim3 ggrid(C_DIM / BN, B_ROWS / BM);  // (8, 128)

    // forward: h1,d1 ; h2,d2 ; z = y + g(y)
    gemm_nt<EPI_ELU ><<<ggrid, GEMM_THREADS>>>(y,  W1, b1, h1, d1, nullptr, 0.f, nullptr);
    gemm_nt<EPI_ELU ><<<ggrid, GEMM_THREADS>>>(h1, W2, b2, h2, d2, nullptr, 0.f, nullptr);
    gemm_nt<EPI_ADDY><<<ggrid, GEMM_THREADS>>>(h2, W3, b3, zout, nullptr, y, 0.f, nullptr);

    // power-series VJP iterations
    const float* wcur = v;
    for (int k = 1; k <= N_ITERS; ++k) {
        gemm_nt<EPI_MULD><<<ggrid, GEMM_THREADS>>>(wcur, w3t, nullptr, t1, nullptr, d2, 0.f, nullptr);
        gemm_nt<EPI_MULD><<<ggrid, GEMM_THREADS>>>(t1,   w2t, nullptr, t2, nullptr, d1, 0.f, nullptr);
        const float alpha = ((k & 1) ? 1.f : -1.f) / (float)k;
        gemm_nt<EPI_LAST><<<ggrid, GEMM_THREADS>>>(t2,   w1t, nullptr, wb, nullptr, v, alpha, ldout);
        wcur = wb;
    }
}